// round 13
// baseline (speedup 1.0000x reference)
#include <cuda_runtime.h>
#include <cuda_fp16.h>
#include <cstdint>

#define N_TOKENS 8192
#define IN_F     4096
#define OUT_F    16384

#define BM 128
#define BN 128
#define BK 64              // fp16 elems per k-chunk = 128B payload per row
#define NKC (IN_F / BK)    // 64
#define NSTAGE 3
#define THREADS 256        // 8 warps, 2x4 grid of 64x32 warp tiles

// smem rows padded 128B -> 144B (LDSM row ptrs on banks 4r%32: conflict-free)
#define ROW_PITCH 144
#define A_OFF   0
#define B_OFF   (BM * ROW_PITCH)                       // 18432
#define STAGE_BYTES ((BM + BN) * ROW_PITCH)            // 36864
#define SMEM_BYTES  (NSTAGE * STAGE_BYTES)             // 110592 (x2 CTAs = 221KB/SM)

// -------- static scratch (no runtime allocation allowed) --------
__device__ __half g_Wh[(size_t)OUT_F * IN_F];     // 128 MB
__device__ __half g_Xh[(size_t)N_TOKENS * IN_F];  // 64 MB

// ---------------- helpers ----------------
__device__ __forceinline__ uint32_t smem_u32(const void* p) {
    uint32_t a;
    asm("{ .reg .u64 t; cvta.to.shared.u64 t, %1; cvt.u32.u64 %0, t; }" : "=r"(a) : "l"(p));
    return a;
}

__device__ __forceinline__ void cp_async16(uint32_t dst, const void* src) {
    asm volatile("cp.async.cg.shared.global [%0], [%1], 16;" :: "r"(dst), "l"(src));
}

__device__ __forceinline__ void ldsm_x4(uint32_t* r, uint32_t a) {
    asm volatile("ldmatrix.sync.aligned.m8n8.x4.shared.b16 {%0,%1,%2,%3}, [%4];"
                 : "=r"(r[0]), "=r"(r[1]), "=r"(r[2]), "=r"(r[3]) : "r"(a));
}

// m16n8k16 fp16 MMA, fp32 accumulate
__device__ __forceinline__ void mma_f16(float* c, const uint32_t* a, uint32_t b0, uint32_t b1) {
    asm volatile(
        "mma.sync.aligned.m16n8k16.row.col.f32.f16.f16.f32 "
        "{%0,%1,%2,%3}, {%4,%5,%6,%7}, {%8,%9}, {%0,%1,%2,%3};"
        : "+f"(c[0]), "+f"(c[1]), "+f"(c[2]), "+f"(c[3])
        : "r"(a[0]), "r"(a[1]), "r"(a[2]), "r"(a[3]), "r"(b0), "r"(b1));
}

// ---------------- fused conversion kernel ----------------
// blocks [0, 32768): W int32 -> fp16; blocks [32768, 49152): x fp32 -> fp16
__global__ void convert_all_kernel(const int* __restrict__ w, const float* __restrict__ x) {
    if (blockIdx.x < 32768) {
        size_t i = ((size_t)blockIdx.x * blockDim.x + threadIdx.x) * 8;
        int4 a = *(const int4*)(w + i);
        int4 b = *(const int4*)(w + i + 4);
        __half2 h0 = __floats2half2_rn((float)a.x, (float)a.y);
        __half2 h1 = __floats2half2_rn((float)a.z, (float)a.w);
        __half2 h2 = __floats2half2_rn((float)b.x, (float)b.y);
        __half2 h3 = __floats2half2_rn((float)b.z, (float)b.w);
        uint4 st;
        st.x = *(unsigned*)&h0; st.y = *(unsigned*)&h1;
        st.z = *(unsigned*)&h2; st.w = *(unsigned*)&h3;
        *(uint4*)(g_Wh + i) = st;
    } else {
        size_t i = ((size_t)(blockIdx.x - 32768) * blockDim.x + threadIdx.x) * 8;
        float4 v0 = *(const float4*)(x + i);
        float4 v1 = *(const float4*)(x + i + 4);
        __half2 h0 = __floats2half2_rn(v0.x, v0.y);
        __half2 h1 = __floats2half2_rn(v0.z, v0.w);
        __half2 h2 = __floats2half2_rn(v1.x, v1.y);
        __half2 h3 = __floats2half2_rn(v1.z, v1.w);
        uint4 st;
        st.x = *(unsigned*)&h0; st.y = *(unsigned*)&h1;
        st.z = *(unsigned*)&h2; st.w = *(unsigned*)&h3;
        *(uint4*)(g_Xh + i) = st;
    }
}

// ---------------- GEMM ----------------
// one stage: A (x) 128 rows x 128B (4 chunks/thread), B (W) 128 rows x 128B
// (4 chunks/thread). load_chunk issues ONE 16B chunk: idx 0-3 = A, idx 4-7 = B.
__device__ __forceinline__ void load_chunk(uint32_t slot, int bm0, int bn0,
                                           int kc, int tid, int idx) {
    if (idx < 4) {
        int ch = idx * 256 + tid;
        int row = ch >> 3, c = ch & 7;
        cp_async16(slot + A_OFF + (uint32_t)(row * ROW_PITCH + c * 16),
                   g_Xh + (size_t)(bm0 + row) * IN_F + (size_t)kc * BK + c * 8);
    } else {
        int ch = (idx - 4) * 256 + tid;
        int row = ch >> 3, c = ch & 7;
        cp_async16(slot + B_OFF + (uint32_t)(row * ROW_PITCH + c * 16),
                   g_Wh + (size_t)(bn0 + row) * IN_F + (size_t)kc * BK + c * 8);
    }
}

__device__ __forceinline__ void load_stage(uint32_t slot, int bm0, int bn0,
                                           int kc, int tid) {
#pragma unroll
    for (int p = 0; p < 8; p++) load_chunk(slot, bm0, bn0, kc, tid, p);
}

__global__ void __launch_bounds__(THREADS, 2)
gemm_kernel(const int* __restrict__ bias, const float* __restrict__ scale_p,
            float* __restrict__ out) {
    extern __shared__ char dsmem[];
    const uint32_t sb = smem_u32(dsmem);
    const int tid = threadIdx.x;

    // supertile rasterization: pm varies fastest in groups of 16 (W L2 reuse)
    const int n_m = N_TOKENS / BM;   // 64
    const int n_n = OUT_F / BN;      // 128
    const int GROUP = 16;
    int pid = blockIdx.x;
    int nig = GROUP * n_n;
    int gid = pid / nig;
    int fm = gid * GROUP;
    int gsz = (GROUP < n_m - fm) ? GROUP : (n_m - fm);
    int pm = fm + (pid % nig) % gsz;
    int pn = (pid % nig) / gsz;
    const int bm0 = pm * BM;
    const int bn0 = pn * BN;

    const int w = tid >> 5, lane = tid & 31;
    const int wm = w & 1, wn = w >> 1;          // 2x4 warp grid, 64x32 tiles
    const int g = lane >> 2, tg = lane & 3;
    const int j = lane & 7, m8 = lane >> 3;

    // ldmatrix lane->row-pointer offsets
    const uint32_t aLdsm =
        (uint32_t)((wm * 64 + j + (m8 & 1) * 8) * ROW_PITCH + (m8 >> 1) * 16);
    const uint32_t bLdsm =
        (uint32_t)((wn * 32 + (m8 >> 1) * 8 + j) * ROW_PITCH + (m8 & 1) * 16);

    float acc[4][4][4];
#pragma unroll
    for (int mt = 0; mt < 4; mt++)
#pragma unroll
        for (int nt = 0; nt < 4; nt++)
#pragma unroll
            for (int r = 0; r < 4; r++) acc[mt][nt][r] = 0.f;

    // prologue: stages 0,1
    load_stage(sb, bm0, bn0, 0, tid);
    asm volatile("cp.async.commit_group;" ::: "memory");
    load_stage(sb + STAGE_BYTES, bm0, bn0, 1, tid);
    asm volatile("cp.async.commit_group;" ::: "memory");

    int s_cur = 0, s_nxt = 2;   // slot of kc, slot of kc+2
    for (int kc = 0; kc < NKC; kc++) {
        // group kc complete; kc+1 still in flight
        asm volatile("cp.async.wait_group 1;" ::: "memory");
        // single barrier: stage-kc visibility AND slot-reuse safety
        // (everyone past compute of kc-1, whose slot kc+2 takes)
        __syncthreads();

        const int kn = kc + 2;
        const bool do_load = (kn < NKC);
        const uint32_t nxt = sb + s_nxt * STAGE_BYTES;
        const uint32_t stg = sb + s_cur * STAGE_BYTES;
        if (++s_cur == NSTAGE) s_cur = 0;
        if (++s_nxt == NSTAGE) s_nxt = 0;

#pragma unroll
        for (int ks = 0; ks < 4; ks++) {         // 4 x k16
            const uint32_t k0 = ks * 32;         // bytes

            // 1) fragment loads first (critical path for this ks's MMAs)
            uint32_t af[4][4];
#pragma unroll
            for (int mt = 0; mt < 4; mt++)
                ldsm_x4(af[mt], stg + A_OFF + aLdsm + k0 + mt * (16 * ROW_PITCH));
            uint32_t bf[2][4];                   // [nt-pair][reg]
#pragma unroll
            for (int bp = 0; bp < 2; bp++)
                ldsm_x4(bf[bp], stg + B_OFF + bLdsm + k0 + bp * (16 * ROW_PITCH));

            // 2) one prefetch chunk, then half the MMAs, then the other chunk
            if (do_load) load_chunk(nxt, bm0, bn0, kn, tid, ks * 2);
#pragma unroll
            for (int nt = 0; nt < 2; nt++) {
                uint32_t b0 = bf[0][nt * 2];
                uint32_t b1 = bf[0][nt * 2 + 1];
#pragma unroll
                for (int mt = 0; mt < 4; mt++)
                    mma_f16(acc[mt][nt], af[mt], b0, b1);
            }
            if (do_load) load_chunk(nxt, bm0, bn0, kn, tid, ks * 2 + 1);
#pragma unroll
            for (int nt = 2; nt < 4; nt++) {
                uint32_t b0 = bf[1][(nt - 2) * 2];
                uint32_t b1 = bf[1][(nt - 2) * 2 + 1];
#pragma unroll
                for (int mt = 0; mt < 4; mt++)
                    mma_f16(acc[mt][nt], af[mt], b0, b1);
            }
        }
        asm volatile("cp.async.commit_group;" ::: "memory");  // fixed group count
    }

    // ---------------- epilogue ----------------
    float ws = __ldg(scale_p);
#pragma unroll
    for (int mt = 0; mt < 4; mt++) {
        int r0 = bm0 + wm * 64 + mt * 16 + g;
#pragma unroll
        for (int nt = 0; nt < 4; nt++) {
            int col = bn0 + wn * 32 + nt * 8 + tg * 2;
            int2 bv = *(const int2*)(bias + col);
            float b0f = ws * (float)bv.x;
            float b1f = ws * (float)bv.y;
            const float* a = acc[mt][nt];
            float2 v;
            v.x = ws * a[0] + b0f;
            v.y = ws * a[1] + b1f;
            *(float2*)(out + (size_t)r0 * OUT_F + col) = v;
            v.x = ws * a[2] + b0f;
            v.y = ws * a[3] + b1f;
            *(float2*)(out + (size_t)(r0 + 8) * OUT_F + col) = v;
        }
    }
}

// ---------------- launch ----------------
extern "C" void kernel_launch(void* const* d_in, const int* in_sizes, int n_in,
                              void* d_out, int out_size) {
    const float* x     = (const float*)d_in[0];
    const int*   wgt   = (const int*)d_in[1];
    const int*   bias  = (const int*)d_in[2];
    const float* scale = (const float*)d_in[3];
    float* out = (float*)d_out;

    convert_all_kernel<<<49152, 256>>>(wgt, x);   // W: 32768 blocks, x: 16384 blocks

    cudaFuncSetAttribute(gemm_kernel, cudaFuncAttributeMaxDynamicSharedMemorySize,
                         SMEM_BYTES);
    gemm_kernel<<<(N_TOKENS / BM) * (OUT_F / BN), THREADS, SMEM_BYTES>>>(bias, scale, out);
}

// round 15
// speedup vs baseline: 1.5169x; 1.5169x over previous
#include <cuda_runtime.h>
#include <cuda_fp16.h>
#include <cstdint>

#define N_TOKENS 8192
#define IN_F     4096
#define OUT_F    16384

#define BM 128
#define BN 128
#define BK 64              // fp16 elems per k-chunk = 128B payload per row
#define NKC (IN_F / BK)    // 64
#define NSTAGE 3
#define THREADS 256        // 8 warps, 2x4 grid of 64x32 warp tiles

// smem rows padded 128B -> 144B (LDSM row ptrs on banks 4r%32: conflict-free)
#define ROW_PITCH 144
#define A_OFF   0
#define B_OFF   (BM * ROW_PITCH)                       // 18432
#define STAGE_BYTES ((BM + BN) * ROW_PITCH)            // 36864
#define SMEM_BYTES  (NSTAGE * STAGE_BYTES)             // 110592 (x2 CTAs = 221KB/SM)

// -------- static scratch (no runtime allocation allowed) --------
__device__ __half g_Wh[(size_t)OUT_F * IN_F];     // 128 MB
__device__ __half g_Xh[(size_t)N_TOKENS * IN_F];  // 64 MB

// ---------------- helpers ----------------
__device__ __forceinline__ uint32_t smem_u32(const void* p) {
    uint32_t a;
    asm("{ .reg .u64 t; cvta.to.shared.u64 t, %1; cvt.u32.u64 %0, t; }" : "=r"(a) : "l"(p));
    return a;
}

__device__ __forceinline__ void cp_async16(uint32_t dst, const void* src) {
    asm volatile("cp.async.cg.shared.global [%0], [%1], 16;" :: "r"(dst), "l"(src));
}

__device__ __forceinline__ void ldsm_x4(uint32_t* r, uint32_t a) {
    asm volatile("ldmatrix.sync.aligned.m8n8.x4.shared.b16 {%0,%1,%2,%3}, [%4];"
                 : "=r"(r[0]), "=r"(r[1]), "=r"(r[2]), "=r"(r[3]) : "r"(a));
}

// m16n8k16 fp16 MMA, fp32 accumulate
__device__ __forceinline__ void mma_f16(float* c, const uint32_t* a, uint32_t b0, uint32_t b1) {
    asm volatile(
        "mma.sync.aligned.m16n8k16.row.col.f32.f16.f16.f32 "
        "{%0,%1,%2,%3}, {%4,%5,%6,%7}, {%8,%9}, {%0,%1,%2,%3};"
        : "+f"(c[0]), "+f"(c[1]), "+f"(c[2]), "+f"(c[3])
        : "r"(a[0]), "r"(a[1]), "r"(a[2]), "r"(a[3]), "r"(b0), "r"(b1));
}

// ---------------- fused conversion kernel ----------------
// blocks [0, 32768): W int32 -> fp16; blocks [32768, 49152): x fp32 -> fp16
__global__ void convert_all_kernel(const int* __restrict__ w, const float* __restrict__ x) {
    if (blockIdx.x < 32768) {
        size_t i = ((size_t)blockIdx.x * blockDim.x + threadIdx.x) * 8;
        int4 a = *(const int4*)(w + i);
        int4 b = *(const int4*)(w + i + 4);
        __half2 h0 = __floats2half2_rn((float)a.x, (float)a.y);
        __half2 h1 = __floats2half2_rn((float)a.z, (float)a.w);
        __half2 h2 = __floats2half2_rn((float)b.x, (float)b.y);
        __half2 h3 = __floats2half2_rn((float)b.z, (float)b.w);
        uint4 st;
        st.x = *(unsigned*)&h0; st.y = *(unsigned*)&h1;
        st.z = *(unsigned*)&h2; st.w = *(unsigned*)&h3;
        *(uint4*)(g_Wh + i) = st;
    } else {
        size_t i = ((size_t)(blockIdx.x - 32768) * blockDim.x + threadIdx.x) * 8;
        float4 v0 = *(const float4*)(x + i);
        float4 v1 = *(const float4*)(x + i + 4);
        __half2 h0 = __floats2half2_rn(v0.x, v0.y);
        __half2 h1 = __floats2half2_rn(v0.z, v0.w);
        __half2 h2 = __floats2half2_rn(v1.x, v1.y);
        __half2 h3 = __floats2half2_rn(v1.z, v1.w);
        uint4 st;
        st.x = *(unsigned*)&h0; st.y = *(unsigned*)&h1;
        st.z = *(unsigned*)&h2; st.w = *(unsigned*)&h3;
        *(uint4*)(g_Xh + i) = st;
    }
}

// ---------------- GEMM ----------------
// one stage: A (x) 128 rows x 128B (4 chunks/thread), B (W) 128 rows x 128B
// (4 chunks/thread). load_part issues 2 of the 8 16B-chunks: one A + one B,
// balanced across the 4 parts (vs R12's all-A-then-all-B split).
__device__ __forceinline__ void load_part(uint32_t slot, int bm0, int bn0,
                                          int kc, int tid, int part) {
    {
        int ch = part * 256 + tid;                 // A chunk `part`
        int row = ch >> 3, c = ch & 7;
        cp_async16(slot + A_OFF + (uint32_t)(row * ROW_PITCH + c * 16),
                   g_Xh + (size_t)(bm0 + row) * IN_F + (size_t)kc * BK + c * 8);
    }
    {
        int ch = part * 256 + tid;                 // B chunk `part`
        int row = ch >> 3, c = ch & 7;
        cp_async16(slot + B_OFF + (uint32_t)(row * ROW_PITCH + c * 16),
                   g_Wh + (size_t)(bn0 + row) * IN_F + (size_t)kc * BK + c * 8);
    }
}

__device__ __forceinline__ void load_stage(uint32_t slot, int bm0, int bn0,
                                           int kc, int tid) {
#pragma unroll
    for (int p = 0; p < 4; p++) load_part(slot, bm0, bn0, kc, tid, p);
}

__global__ void __launch_bounds__(THREADS, 2)
gemm_kernel(const int* __restrict__ bias, const float* __restrict__ scale_p,
            float* __restrict__ out) {
    extern __shared__ char dsmem[];
    const uint32_t sb = smem_u32(dsmem);
    const int tid = threadIdx.x;

    // supertile rasterization: pm varies fastest in groups of 16 (W L2 reuse)
    const int n_m = N_TOKENS / BM;   // 64
    const int n_n = OUT_F / BN;      // 128
    const int GROUP = 16;
    int pid = blockIdx.x;
    int nig = GROUP * n_n;
    int gid = pid / nig;
    int fm = gid * GROUP;
    int gsz = (GROUP < n_m - fm) ? GROUP : (n_m - fm);
    int pm = fm + (pid % nig) % gsz;
    int pn = (pid % nig) / gsz;
    const int bm0 = pm * BM;
    const int bn0 = pn * BN;

    const int w = tid >> 5, lane = tid & 31;
    const int wm = w & 1, wn = w >> 1;          // 2x4 warp grid, 64x32 tiles
    const int g = lane >> 2, tg = lane & 3;
    const int j = lane & 7, m8 = lane >> 3;

    // ldmatrix lane->row-pointer offsets
    const uint32_t aLdsm =
        (uint32_t)((wm * 64 + j + (m8 & 1) * 8) * ROW_PITCH + (m8 >> 1) * 16);
    const uint32_t bLdsm =
        (uint32_t)((wn * 32 + (m8 >> 1) * 8 + j) * ROW_PITCH + (m8 & 1) * 16);

    float acc[4][4][4];
#pragma unroll
    for (int mt = 0; mt < 4; mt++)
#pragma unroll
        for (int nt = 0; nt < 4; nt++)
#pragma unroll
            for (int r = 0; r < 4; r++) acc[mt][nt][r] = 0.f;

    // prologue: stages 0,1
    load_stage(sb, bm0, bn0, 0, tid);
    asm volatile("cp.async.commit_group;" ::: "memory");
    load_stage(sb + STAGE_BYTES, bm0, bn0, 1, tid);
    asm volatile("cp.async.commit_group;" ::: "memory");

    int s_cur = 0, s_nxt = 2;   // slot of kc, slot of kc+2
    for (int kc = 0; kc < NKC; kc++) {
        // group kc complete; kc+1 still in flight
        asm volatile("cp.async.wait_group 1;" ::: "memory");
        // single barrier: stage-kc visibility AND slot-reuse safety
        // (everyone past compute of kc-1, whose slot kc+2 takes)
        __syncthreads();

        const int kn = kc + 2;
        const bool do_load = (kn < NKC);
        const uint32_t nxt = sb + s_nxt * STAGE_BYTES;
        const uint32_t stg = sb + s_cur * STAGE_BYTES;
        if (++s_cur == NSTAGE) s_cur = 0;
        if (++s_nxt == NSTAGE) s_nxt = 0;

#pragma unroll
        for (int ks = 0; ks < 4; ks++) {         // 4 x k16
            // interleave 1/4 of the next-stage cp.async burst per ks
            // (issued at the head: async stores drain under the MMA block)
            if (do_load) load_part(nxt, bm0, bn0, kn, tid, ks);

            const uint32_t k0 = ks * 32;         // bytes
            uint32_t af[4][4];
#pragma unroll
            for (int mt = 0; mt < 4; mt++)
                ldsm_x4(af[mt], stg + A_OFF + aLdsm + k0 + mt * (16 * ROW_PITCH));
            uint32_t bf[2][4];                   // [nt-pair][reg]
#pragma unroll
            for (int bp = 0; bp < 2; bp++)
                ldsm_x4(bf[bp], stg + B_OFF + bLdsm + k0 + bp * (16 * ROW_PITCH));
            // contiguous MMA block (do NOT split: R13 showed a seam here costs 50%)
#pragma unroll
            for (int nt = 0; nt < 4; nt++) {
                uint32_t b0 = bf[nt >> 1][(nt & 1) * 2];
                uint32_t b1 = bf[nt >> 1][(nt & 1) * 2 + 1];
#pragma unroll
                for (int mt = 0; mt < 4; mt++)
                    mma_f16(acc[mt][nt], af[mt], b0, b1);
            }
        }
        asm volatile("cp.async.commit_group;" ::: "memory");  // fixed group count
    }

    // ---------------- epilogue ----------------
    float ws = __ldg(scale_p);
#pragma unroll
    for (int mt = 0; mt < 4; mt++) {
        int r0 = bm0 + wm * 64 + mt * 16 + g;
#pragma unroll
        for (int nt = 0; nt < 4; nt++) {
            int col = bn0 + wn * 32 + nt * 8 + tg * 2;
            int2 bv = *(const int2*)(bias + col);
            float b0f = ws * (float)bv.x;
            float b1f = ws * (float)bv.y;
            const float* a = acc[mt][nt];
            float2 v;
            v.x = ws * a[0] + b0f;
            v.y = ws * a[1] + b1f;
            *(float2*)(out + (size_t)r0 * OUT_F + col) = v;
            v.x = ws * a[2] + b0f;
            v.y = ws * a[3] + b1f;
            *(float2*)(out + (size_t)(r0 + 8) * OUT_F + col) = v;
        }
    }
}

// ---------------- launch ----------------
extern "C" void kernel_launch(void* const* d_in, const int* in_sizes, int n_in,
                              void* d_out, int out_size) {
    const float* x     = (const float*)d_in[0];
    const int*   wgt   = (const int*)d_in[1];
    const int*   bias  = (const int*)d_in[2];
    const float* scale = (const float*)d_in[3];
    float* out = (float*)d_out;

    convert_all_kernel<<<49152, 256>>>(wgt, x);   // W: 32768 blocks, x: 16384 blocks

    cudaFuncSetAttribute(gemm_kernel, cudaFuncAttributeMaxDynamicSharedMemorySize,
                         SMEM_BYTES);
    gemm_kernel<<<(N_TOKENS / BM) * (OUT_F / BN), THREADS, SMEM_BYTES>>>(bias, scale, out);
}

// round 16
// speedup vs baseline: 1.5243x; 1.0049x over previous
#include <cuda_runtime.h>
#include <cuda_fp16.h>
#include <cstdint>

#define N_TOKENS 8192
#define IN_F     4096
#define OUT_F    16384

#define BM 128
#define BN 128
#define BK 64              // fp16 elems per k-chunk = 128B payload per row
#define NKC (IN_F / BK)    // 64
#define NSTAGE 3
#define THREADS 256        // 8 warps, 2x4 grid of 64x32 warp tiles

// smem rows padded 128B -> 144B (LDSM row ptrs on banks 4r%32: conflict-free)
#define ROW_PITCH 144
#define A_OFF   0
#define B_OFF   (BM * ROW_PITCH)                       // 18432
#define STAGE_BYTES ((BM + BN) * ROW_PITCH)            // 36864
#define SMEM_BYTES  (NSTAGE * STAGE_BYTES)             // 110592 (x2 CTAs = 221KB/SM)

// -------- static scratch (no runtime allocation allowed) --------
__device__ __half g_Wh[(size_t)OUT_F * IN_F];     // 128 MB
__device__ __half g_Xh[(size_t)N_TOKENS * IN_F];  // 64 MB

// ---------------- helpers ----------------
__device__ __forceinline__ uint32_t smem_u32(const void* p) {
    uint32_t a;
    asm("{ .reg .u64 t; cvta.to.shared.u64 t, %1; cvt.u32.u64 %0, t; }" : "=r"(a) : "l"(p));
    return a;
}

__device__ __forceinline__ void cp_async16(uint32_t dst, const void* src) {
    asm volatile("cp.async.cg.shared.global [%0], [%1], 16;" :: "r"(dst), "l"(src));
}

__device__ __forceinline__ void ldsm_x4(uint32_t* r, uint32_t a) {
    asm volatile("ldmatrix.sync.aligned.m8n8.x4.shared.b16 {%0,%1,%2,%3}, [%4];"
                 : "=r"(r[0]), "=r"(r[1]), "=r"(r[2]), "=r"(r[3]) : "r"(a));
}

// m16n8k16 fp16 MMA, fp32 accumulate
__device__ __forceinline__ void mma_f16(float* c, const uint32_t* a, uint32_t b0, uint32_t b1) {
    asm volatile(
        "mma.sync.aligned.m16n8k16.row.col.f32.f16.f16.f32 "
        "{%0,%1,%2,%3}, {%4,%5,%6,%7}, {%8,%9}, {%0,%1,%2,%3};"
        : "+f"(c[0]), "+f"(c[1]), "+f"(c[2]), "+f"(c[3])
        : "r"(a[0]), "r"(a[1]), "r"(a[2]), "r"(a[3]), "r"(b0), "r"(b1));
}

// evict-streaming float2 store: keep write-once output from displacing W/A in L2
__device__ __forceinline__ void stg_cs_f2(float* p, float vx, float vy) {
    asm volatile("st.global.cs.v2.f32 [%0], {%1, %2};" :: "l"(p), "f"(vx), "f"(vy)
                 : "memory");
}

// ---------------- fused conversion kernel ----------------
// blocks [0, 32768): W int32 -> fp16; blocks [32768, 49152): x fp32 -> fp16
__global__ void convert_all_kernel(const int* __restrict__ w, const float* __restrict__ x) {
    if (blockIdx.x < 32768) {
        size_t i = ((size_t)blockIdx.x * blockDim.x + threadIdx.x) * 8;
        int4 a = *(const int4*)(w + i);
        int4 b = *(const int4*)(w + i + 4);
        __half2 h0 = __floats2half2_rn((float)a.x, (float)a.y);
        __half2 h1 = __floats2half2_rn((float)a.z, (float)a.w);
        __half2 h2 = __floats2half2_rn((float)b.x, (float)b.y);
        __half2 h3 = __floats2half2_rn((float)b.z, (float)b.w);
        uint4 st;
        st.x = *(unsigned*)&h0; st.y = *(unsigned*)&h1;
        st.z = *(unsigned*)&h2; st.w = *(unsigned*)&h3;
        *(uint4*)(g_Wh + i) = st;
    } else {
        size_t i = ((size_t)(blockIdx.x - 32768) * blockDim.x + threadIdx.x) * 8;
        float4 v0 = *(const float4*)(x + i);
        float4 v1 = *(const float4*)(x + i + 4);
        __half2 h0 = __floats2half2_rn(v0.x, v0.y);
        __half2 h1 = __floats2half2_rn(v0.z, v0.w);
        __half2 h2 = __floats2half2_rn(v1.x, v1.y);
        __half2 h3 = __floats2half2_rn(v1.z, v1.w);
        uint4 st;
        st.x = *(unsigned*)&h0; st.y = *(unsigned*)&h1;
        st.z = *(unsigned*)&h2; st.w = *(unsigned*)&h3;
        *(uint4*)(g_Xh + i) = st;
    }
}

// ---------------- GEMM ----------------
// one stage: A (x) 128 rows x 128B (4 chunks/thread), B (W) 128 rows x 128B
// (4 chunks/thread). load_part issues 2 of the 8 16B-chunks: one A + one B.
__device__ __forceinline__ void load_part(uint32_t slot, int bm0, int bn0,
                                          int kc, int tid, int part) {
    {
        int ch = part * 256 + tid;                 // A chunk `part`
        int row = ch >> 3, c = ch & 7;
        cp_async16(slot + A_OFF + (uint32_t)(row * ROW_PITCH + c * 16),
                   g_Xh + (size_t)(bm0 + row) * IN_F + (size_t)kc * BK + c * 8);
    }
    {
        int ch = part * 256 + tid;                 // B chunk `part`
        int row = ch >> 3, c = ch & 7;
        cp_async16(slot + B_OFF + (uint32_t)(row * ROW_PITCH + c * 16),
                   g_Wh + (size_t)(bn0 + row) * IN_F + (size_t)kc * BK + c * 8);
    }
}

__device__ __forceinline__ void load_stage(uint32_t slot, int bm0, int bn0,
                                           int kc, int tid) {
#pragma unroll
    for (int p = 0; p < 4; p++) load_part(slot, bm0, bn0, kc, tid, p);
}

__global__ void __launch_bounds__(THREADS, 2)
gemm_kernel(const int* __restrict__ bias, const float* __restrict__ scale_p,
            float* __restrict__ out) {
    extern __shared__ char dsmem[];
    const uint32_t sb = smem_u32(dsmem);
    const int tid = threadIdx.x;

    // supertile rasterization: pm varies fastest in groups of 16 (W L2 reuse)
    const int n_m = N_TOKENS / BM;   // 64
    const int n_n = OUT_F / BN;      // 128
    const int GROUP = 16;
    int pid = blockIdx.x;
    int nig = GROUP * n_n;
    int gid = pid / nig;
    int fm = gid * GROUP;
    int gsz = (GROUP < n_m - fm) ? GROUP : (n_m - fm);
    int pm = fm + (pid % nig) % gsz;
    int pn = (pid % nig) / gsz;
    const int bm0 = pm * BM;
    const int bn0 = pn * BN;

    const int w = tid >> 5, lane = tid & 31;
    const int wm = w & 1, wn = w >> 1;          // 2x4 warp grid, 64x32 tiles
    const int g = lane >> 2, tg = lane & 3;
    const int j = lane & 7, m8 = lane >> 3;

    // ldmatrix lane->row-pointer offsets
    const uint32_t aLdsm =
        (uint32_t)((wm * 64 + j + (m8 & 1) * 8) * ROW_PITCH + (m8 >> 1) * 16);
    const uint32_t bLdsm =
        (uint32_t)((wn * 32 + (m8 >> 1) * 8 + j) * ROW_PITCH + (m8 & 1) * 16);

    const float ws = __ldg(scale_p);

    float acc[4][4][4];
#pragma unroll
    for (int mt = 0; mt < 4; mt++)
#pragma unroll
        for (int nt = 0; nt < 4; nt++)
#pragma unroll
            for (int r = 0; r < 4; r++) acc[mt][nt][r] = 0.f;

    // prologue: stages 0,1
    load_stage(sb, bm0, bn0, 0, tid);
    asm volatile("cp.async.commit_group;" ::: "memory");
    load_stage(sb + STAGE_BYTES, bm0, bn0, 1, tid);
    asm volatile("cp.async.commit_group;" ::: "memory");

    int s_cur = 0, s_nxt = 2;   // slot of kc, slot of kc+2
    for (int kc = 0; kc < NKC; kc++) {
        // group kc complete; kc+1 still in flight
        asm volatile("cp.async.wait_group 1;" ::: "memory");
        // single barrier: stage-kc visibility AND slot-reuse safety
        // (everyone past compute of kc-1, whose slot kc+2 takes)
        __syncthreads();

        const int kn = kc + 2;
        const bool do_load = (kn < NKC);
        const uint32_t nxt = sb + s_nxt * STAGE_BYTES;
        const uint32_t stg = sb + s_cur * STAGE_BYTES;
        if (++s_cur == NSTAGE) s_cur = 0;
        if (++s_nxt == NSTAGE) s_nxt = 0;

#pragma unroll
        for (int ks = 0; ks < 4; ks++) {         // 4 x k16
            // interleave 1/4 of the next-stage cp.async burst per ks
            // (issued at the head: async stores drain under the MMA block)
            if (do_load) load_part(nxt, bm0, bn0, kn, tid, ks);

            const uint32_t k0 = ks * 32;         // bytes
            uint32_t af[4][4];
#pragma unroll
            for (int mt = 0; mt < 4; mt++)
                ldsm_x4(af[mt], stg + A_OFF + aLdsm + k0 + mt * (16 * ROW_PITCH));
            uint32_t bf[2][4];                   // [nt-pair][reg]
#pragma unroll
            for (int bp = 0; bp < 2; bp++)
                ldsm_x4(bf[bp], stg + B_OFF + bLdsm + k0 + bp * (16 * ROW_PITCH));
            // contiguous MMA block (do NOT split: R13 showed a seam here costs 50%)
#pragma unroll
            for (int nt = 0; nt < 4; nt++) {
                uint32_t b0 = bf[nt >> 1][(nt & 1) * 2];
                uint32_t b1 = bf[nt >> 1][(nt & 1) * 2 + 1];
#pragma unroll
                for (int mt = 0; mt < 4; mt++)
                    mma_f16(acc[mt][nt], af[mt], b0, b1);
            }
        }
        asm volatile("cp.async.commit_group;" ::: "memory");  // fixed group count
    }

    // ---------------- epilogue (evict-streaming output stores) ----------------
#pragma unroll
    for (int mt = 0; mt < 4; mt++) {
        int r0 = bm0 + wm * 64 + mt * 16 + g;
#pragma unroll
        for (int nt = 0; nt < 4; nt++) {
            int col = bn0 + wn * 32 + nt * 8 + tg * 2;
            int2 bv = *(const int2*)(bias + col);
            float b0f = ws * (float)bv.x;
            float b1f = ws * (float)bv.y;
            const float* a = acc[mt][nt];
            stg_cs_f2(out + (size_t)r0 * OUT_F + col,
                      ws * a[0] + b0f, ws * a[1] + b1f);
            stg_cs_f2(out + (size_t)(r0 + 8) * OUT_F + col,
                      ws * a[2] + b0f, ws * a[3] + b1f);
        }
    }
}

// ---------------- launch ----------------
extern "C" void kernel_launch(void* const* d_in, const int* in_sizes, int n_in,
                              void* d_out, int out_size) {
    const float* x     = (const float*)d_in[0];
    const int*   wgt   = (const int*)d_in[1];
    const int*   bias  = (const int*)d_in[2];
    const float* scale = (const float*)d_in[3];
    float* out = (float*)d_out;

    convert_all_kernel<<<49152, 256>>>(wgt, x);   // W: 32768 blocks, x: 16384 blocks

    cudaFuncSetAttribute(gemm_kernel, cudaFuncAttributeMaxDynamicSharedMemorySize,
                         SMEM_BYTES);
    gemm_kernel<<<(N_TOKENS / BM) * (OUT_F / BN), THREADS, SMEM_BYTES>>>(bias, scale, out);
}